// round 14
// baseline (speedup 1.0000x reference)
#include <cuda_runtime.h>
#include <cuda_bf16.h>
#include <cstdint>

// GAT: B=4, N=4096, C=64
// out = elu( softmax_j( mask(adj>0.5, lrelu(s1+s2)) ) @ h )
// R13: warp-specialized producer/consumer with named barriers.
//   warps 0-3: consumers (MMA 16x64 tile each, B-tile cp.async, epilogue)
//   warps 4-7: producers (adj cp.async, w = max(E1*E2, F1*F2), W stores, lsum)
//   exp factorization: exp2(lrelu(u)) = max(exp2(u), exp2(0.2u)) = max(E1E2, F1F2)

#define GB 4
#define GN 4096
#define GC 64
#define TI 64
#define TJ 64
#define NTILES (GN / TJ)
#define THRESH 0.5f

// dynamic smem layout (per CTA): adj 2 stages, B 2 stages, W 2 stages
#define ASTG0   0           // 2 x 16 KB (64 rows x 256B fp32)
#define BSTG0   32768       // 2 x 16 KB (BH 8KB + BL 8KB)
#define WSTG0   65536       // 2 x 16 KB (WH 8KB + WL 8KB)
#define B_HI    0
#define B_LO    8192
#define W_HI    0
#define W_LO    8192
#define STG     16384
#define DSMEM_BYTES (98304 + 1024)

// named barrier ids (count 256 unless noted)
#define BAR_FULL0   1   // +s
#define BAR_EMPTY0  3   // +s
#define BAR_CONS    5   // consumers only, count 128
#define BAR_DONE    6

__device__ float g_e1[GB * GN];
__device__ float g_f1[GB * GN];
__device__ float g_e2[GB * GN];
__device__ float g_f2[GB * GN];
__device__ __nv_bfloat16 g_hh[GB * GN * GC];
__device__ __nv_bfloat16 g_hl[GB * GN * GC];

// ---------------------------------------------------------------- helpers
static __device__ __forceinline__ uint32_t smem_u32(const void* p) {
    uint32_t a;
    asm("{ .reg .u64 t; cvta.to.shared.u64 t, %1; cvt.u32.u64 %0, t; }"
        : "=r"(a) : "l"(p));
    return a;
}
static __device__ __forceinline__ uint32_t cvt_bf16x2(float lo, float hi) {
    uint32_t r;
    asm("cvt.rn.bf16x2.f32 %0, %1, %2;" : "=r"(r) : "f"(hi), "f"(lo));
    return r;
}
static __device__ __forceinline__ uint32_t sw128(uint32_t b) {
    return b ^ ((b >> 3) & 0x70);
}
#define CP16(dst, src) \
    asm volatile("cp.async.cg.shared.global [%0], [%1], 16;" \
                 :: "r"(dst), "l"(src) : "memory")
#define CP_COMMIT() asm volatile("cp.async.commit_group;" ::: "memory")
#define CP_WAIT1()  asm volatile("cp.async.wait_group 1;" ::: "memory")
#define CP_WAIT0()  asm volatile("cp.async.wait_group 0;" ::: "memory")
#define BARS(id, cnt) \
    asm volatile("bar.sync %0, %1;" :: "r"(id), "r"(cnt) : "memory")
#define BARA(id, cnt) \
    asm volatile("bar.arrive %0, %1;" :: "r"(id), "r"(cnt) : "memory")

static __device__ __forceinline__ void ldmx4(uint32_t* r, uint32_t addr) {
    asm volatile("ldmatrix.sync.aligned.m8n8.x4.shared.b16 {%0,%1,%2,%3}, [%4];"
        : "=r"(r[0]), "=r"(r[1]), "=r"(r[2]), "=r"(r[3]) : "r"(addr));
}
static __device__ __forceinline__ void ldmx4t(uint32_t* r, uint32_t addr) {
    asm volatile("ldmatrix.sync.aligned.m8n8.x4.trans.shared.b16 {%0,%1,%2,%3}, [%4];"
        : "=r"(r[0]), "=r"(r[1]), "=r"(r[2]), "=r"(r[3]) : "r"(addr));
}
static __device__ __forceinline__ void mma_bf16(float* d, const uint32_t* a,
                                                uint32_t b0, uint32_t b1) {
    asm volatile(
        "mma.sync.aligned.m16n8k16.row.col.f32.bf16.bf16.f32 "
        "{%0,%1,%2,%3}, {%4,%5,%6,%7}, {%8,%9}, {%0,%1,%2,%3};"
        : "+f"(d[0]), "+f"(d[1]), "+f"(d[2]), "+f"(d[3])
        : "r"(a[0]), "r"(a[1]), "r"(a[2]), "r"(a[3]), "r"(b0), "r"(b1));
}

// ---------------------------------------------------------------- kernel 1
__global__ void gat_scores_kernel(const float* __restrict__ h,
                                  const float* __restrict__ a) {
    int warp = (blockIdx.x * blockDim.x + threadIdx.x) >> 5;
    int lane = threadIdx.x & 31;
    if (warp >= GB * GN) return;
    const float* row = h + (size_t)warp * GC;
    float v0 = row[lane];
    float v1 = row[lane + 32];

    __nv_bfloat16 h0 = __float2bfloat16_rn(v0);
    __nv_bfloat16 h1 = __float2bfloat16_rn(v1);
    g_hh[warp * GC + lane]      = h0;
    g_hh[warp * GC + lane + 32] = h1;
    g_hl[warp * GC + lane]      = __float2bfloat16_rn(v0 - __bfloat162float(h0));
    g_hl[warp * GC + lane + 32] = __float2bfloat16_rn(v1 - __bfloat162float(h1));

    float p1 = v0 * a[lane]      + v1 * a[lane + 32];
    float p2 = v0 * a[GC + lane] + v1 * a[GC + lane + 32];
#pragma unroll
    for (int o = 16; o; o >>= 1) {
        p1 += __shfl_xor_sync(0xFFFFFFFFu, p1, o);
        p2 += __shfl_xor_sync(0xFFFFFFFFu, p2, o);
    }
    const float LOG2E = 1.4426950408889634f;
    if (lane == 0) {
        float t1 = p1 * LOG2E, t2 = p2 * LOG2E;
        g_e1[warp] = exp2f(t1);
        g_f1[warp] = exp2f(0.2f * t1);
        g_e2[warp] = exp2f(t2);
        g_f2[warp] = exp2f(0.2f * t2);
    }
}

// ---------------------------------------------------------------- kernel 2
__global__ __launch_bounds__(256, 2)
void gat_main_kernel(const float* __restrict__ adj,
                     float* __restrict__ out) {
    extern __shared__ char smem_raw[];
    __shared__ float sh_l[TI];

    const int t    = threadIdx.x;
    const int wid  = t >> 5;
    const int lane = t & 31;
    const int b    = blockIdx.y;
    const int i0   = blockIdx.x * TI;

    uint32_t raw_u32 = smem_u32(smem_raw);
    uint32_t sbu = (raw_u32 + 1023u) & ~1023u;

    if (wid >= 4) {
        // ================= PRODUCER (warps 4-7) =================
        const int pt  = t - 128;          // 0..127
        const int r0  = pt >> 4;          // 0..7 (rows r0 + 8k)
        const int jj0 = (pt & 15) * 4;    // cols jj0..+3
        if (pt < TI) sh_l[pt] = 0.0f;

        float E1[8], F1[8];
#pragma unroll
        for (int k = 0; k < 8; k++) {
            int row = b * GN + i0 + r0 + 8 * k;
            E1[k] = g_e1[row];
            F1[k] = g_f1[row];
        }
        float lsum[8] = {0.f, 0.f, 0.f, 0.f, 0.f, 0.f, 0.f, 0.f};

        const float* pa  = adj + (size_t)(i0 + r0) * GN + jj0;
        const float* pe2 = g_e2 + b * GN + jj0;
        const float* pf2 = g_f2 + b * GN + jj0;

        const uint32_t adst  = sbu + ASTG0 + (uint32_t)(r0 * 256 + (pt & 15) * 16);
        const uint32_t wbase = sw128((uint32_t)(r0 * 128 + jj0 * 2));

        // prologue: adj(0) -> astg[0]; E2F2(0) regs
#pragma unroll
        for (int k = 0; k < 8; k++)
            CP16(adst + k * 2048, pa + (size_t)(8 * k) * GN);
        CP_COMMIT();
        float4 e2v = __ldg((const float4*)pe2);
        float4 f2v = __ldg((const float4*)pf2);

        for (int tile = 0; tile < NTILES; tile++) {
            const int s = tile & 1;
            BARS(BAR_EMPTY0 + s, 256);               // W[s] free

            // issue adj(t+1) into other adj stage (self-copied mapping)
            if (tile + 1 < NTILES) {
                const float* pan = pa + (size_t)(tile + 1) * TJ;
                uint32_t ad = adst + (uint32_t)(((tile + 1) & 1) * STG);
#pragma unroll
                for (int k = 0; k < 8; k++)
                    CP16(ad + k * 2048, pan + (size_t)(8 * k) * GN);
            }
            CP_COMMIT();
            CP_WAIT1();                              // adj(t) ready (self-read)

            const uint32_t ard  = adst + (uint32_t)((tile & 1) * STG);
            const uint32_t wstg = sbu + WSTG0 + s * STG;
#pragma unroll
            for (int k = 0; k < 8; k++) {
                float4 av;
                asm volatile("ld.shared.v4.f32 {%0,%1,%2,%3}, [%4];"
                             : "=f"(av.x), "=f"(av.y), "=f"(av.z), "=f"(av.w)
                             : "r"(ard + k * 2048));
                float w0 = (av.x > THRESH) ? fmaxf(E1[k] * e2v.x, F1[k] * f2v.x) : 0.f;
                float w1 = (av.y > THRESH) ? fmaxf(E1[k] * e2v.y, F1[k] * f2v.y) : 0.f;
                float w2 = (av.z > THRESH) ? fmaxf(E1[k] * e2v.z, F1[k] * f2v.z) : 0.f;
                float w3 = (av.w > THRESH) ? fmaxf(E1[k] * e2v.w, F1[k] * f2v.w) : 0.f;
                lsum[k] += (w0 + w1) + (w2 + w3);
                uint32_t h01 = cvt_bf16x2(w0, w1);
                uint32_t h23 = cvt_bf16x2(w2, w3);
                float f0 = __uint_as_float(h01 << 16);
                float f1 = __uint_as_float(h01 & 0xFFFF0000u);
                float f2 = __uint_as_float(h23 << 16);
                float f3 = __uint_as_float(h23 & 0xFFFF0000u);
                uint32_t l01 = cvt_bf16x2(w0 - f0, w1 - f1);
                uint32_t l23 = cvt_bf16x2(w2 - f2, w3 - f3);
                asm volatile("st.shared.v2.b32 [%0], {%1,%2};"
                             :: "r"(wstg + W_HI + wbase + k * 1024),
                                "r"(h01), "r"(h23) : "memory");
                asm volatile("st.shared.v2.b32 [%0], {%1,%2};"
                             :: "r"(wstg + W_LO + wbase + k * 1024),
                                "r"(l01), "r"(l23) : "memory");
            }

            // prefetch E2/F2(t+1)
            {
                int jn = (tile + 1 < NTILES) ? (tile + 1) * TJ : 0;
                e2v = __ldg((const float4*)(pe2 + jn));
                f2v = __ldg((const float4*)(pf2 + jn));
            }
            BARA(BAR_FULL0 + s, 256);                // W[s] ready
        }

        CP_WAIT0();
#pragma unroll
        for (int k = 0; k < 8; k++)
            atomicAdd(&sh_l[r0 + 8 * k], lsum[k]);
        BARA(BAR_DONE, 256);
        return;
    }

    // ================= CONSUMER (warps 0-3) =================
    const int c = wid;                    // rows c*16..+15, cols 0..63

    // pre-arrive both EMPTY barriers so producers can fill W(0), W(1)
    BARA(BAR_EMPTY0 + 0, 256);
    BARA(BAR_EMPTY0 + 1, 256);

    const __nv_bfloat16* phh = g_hh + (size_t)b * GN * GC;
    const __nv_bfloat16* phl = g_hl + (size_t)b * GN * GC;

    // prologue: B(0) -> bstg[0]
    {
        uint32_t bstg = sbu + BSTG0;
#pragma unroll
        for (int k = 0; k < 4; k++) {
            int q = t + 128 * k;
            int j = q >> 3, cc = q & 7;
            uint32_t off = sw128((uint32_t)(j * 128 + cc * 16));
            CP16(bstg + B_HI + off, phh + j * GC + cc * 8);
            CP16(bstg + B_LO + off, phl + j * GC + cc * 8);
        }
        CP_COMMIT();
    }

    const uint32_t xr     = (uint32_t)(lane & 7) << 4;
    const uint32_t a_base = (uint32_t)((c * 16 + (lane & 15)) * 128 + (lane & 16));
    const uint32_t b_base = (uint32_t)((lane & 15) * 128 + (lane & 16));

    float acc[8][4];
#pragma unroll
    for (int nn = 0; nn < 8; nn++)
#pragma unroll
        for (int q = 0; q < 4; q++) acc[nn][q] = 0.0f;

    for (int tile = 0; tile < NTILES; tile++) {
        const int s = tile & 1;
        BARS(BAR_FULL0 + s, 256);          // W(t) ready; all consumers at t

        // issue B(t+1) into other B stage (safe: all consumers past MMA(t-1))
        if (tile + 1 < NTILES) {
            uint32_t bstgN = sbu + BSTG0 + ((tile + 1) & 1) * STG;
            const __nv_bfloat16* hh = phh + (size_t)(tile + 1) * TJ * GC;
            const __nv_bfloat16* hl = phl + (size_t)(tile + 1) * TJ * GC;
#pragma unroll
            for (int k = 0; k < 4; k++) {
                int q = t + 128 * k;
                int j = q >> 3, cc = q & 7;
                uint32_t off = sw128((uint32_t)(j * 128 + cc * 16));
                CP16(bstgN + B_HI + off, hh + j * GC + cc * 8);
                CP16(bstgN + B_LO + off, hl + j * GC + cc * 8);
            }
        }
        CP_COMMIT();
        CP_WAIT1();                        // my B(t) copies done
        BARS(BAR_CONS, 128);               // cross-consumer B(t) visibility

        const uint32_t wstg = sbu + WSTG0 + s * STG;
        const uint32_t bstg = sbu + BSTG0 + (tile & 1) * STG;
        const uint32_t whb = wstg + W_HI;
        const uint32_t wlb = wstg + W_LO;
        const uint32_t bhb = bstg + B_HI;
        const uint32_t blb = bstg + B_LO;
#pragma unroll
        for (int kk = 0; kk < 4; kk++) {
            uint32_t ahi[4], alo[4];
            uint32_t a_off = (a_base + kk * 32) ^ xr;
            ldmx4(ahi, whb + a_off);
            ldmx4(alo, wlb + a_off);
            uint32_t bh[16], bl[16];
#pragma unroll
            for (int np = 0; np < 4; np++) {
                uint32_t b_off = (b_base + kk * 2048 + np * 32) ^ xr;
                ldmx4t(&bh[np * 4], bhb + b_off);
                ldmx4t(&bl[np * 4], blb + b_off);
            }
#pragma unroll
            for (int nn = 0; nn < 8; nn++) {
                int base = (nn >> 1) * 4 + (nn & 1) * 2;
                mma_bf16(acc[nn], ahi, bh[base], bh[base + 1]);
                mma_bf16(acc[nn], ahi, bl[base], bl[base + 1]);
                mma_bf16(acc[nn], alo, bh[base], bh[base + 1]);
            }
        }
        BARA(BAR_EMPTY0 + s, 256);         // W[s] consumed
    }

    CP_WAIT0();
    BARS(BAR_DONE, 256);                   // producers' lsum in sh_l

    // ---- epilogue: normalize + ELU + store (rows c*16..+15, cols 0..63) ----
    {
        int g  = lane >> 2;
        int qc = (lane & 3) * 2;
        int ra = c * 16 + g;
        int rb = ra + 8;
        float la = 1.0f / sh_l[ra];
        float lb = 1.0f / sh_l[rb];
        float* oa = out + ((size_t)b * GN + i0 + ra) * GC;
        float* ob = out + ((size_t)b * GN + i0 + rb) * GC;
#pragma unroll
        for (int nn = 0; nn < 8; nn++) {
            int cc = nn * 8 + qc;
            float v0 = acc[nn][0] * la, v1 = acc[nn][1] * la;
            float v2 = acc[nn][2] * lb, v3 = acc[nn][3] * lb;
            float2 pa2, pb2;
            pa2.x = (v0 > 0.f) ? v0 : expm1f(v0);
            pa2.y = (v1 > 0.f) ? v1 : expm1f(v1);
            pb2.x = (v2 > 0.f) ? v2 : expm1f(v2);
            pb2.y = (v3 > 0.f) ? v3 : expm1f(v3);
            *(float2*)(oa + cc) = pa2;
            *(float2*)(ob + cc) = pb2;
        }
    }
}

// ---------------------------------------------------------------- launch
extern "C" void kernel_launch(void* const* d_in, const int* in_sizes, int n_in,
                              void* d_out, int out_size) {
    const float* input = (const float*)d_in[0];   // (B, N, C)
    const float* adj   = (const float*)d_in[1];   // (N, N)
    const float* a     = (const float*)d_in[2];   // (2C, 1)
    float* out = (float*)d_out;                   // (B, N, C)

    gat_scores_kernel<<<(GB * GN) / 8, 256>>>(input, a);

    cudaFuncSetAttribute(gat_main_kernel,
                         cudaFuncAttributeMaxDynamicSharedMemorySize, DSMEM_BYTES);
    dim3 grid(GN / TI, GB);
    gat_main_kernel<<<grid, 256, DSMEM_BYTES>>>(adj, out);
}

// round 16
// speedup vs baseline: 1.5244x; 1.5244x over previous
#include <cuda_runtime.h>
#include <cuda_bf16.h>
#include <cstdint>

// GAT: B=4, N=4096, C=64
// out = elu( softmax_j( mask(adj>0.5, lrelu(s1+s2)) ) @ h )
// R14: R10 schedule (best: 115.5us) + exp factorization:
//      exp2(lrelu(s1+s2)) = max(E1*E2, F1*F2), E=exp2(t), F=exp2(0.2t)
//      -> phase B has ZERO MUFU ops in the main kernel.

#define GB 4
#define GN 4096
#define GC 64
#define TI 64
#define TJ 64
#define NTILES (GN / TJ)
#define THRESH 0.5f

#define BSTG_SZ 16384     // BH 8KB + BL 8KB
#define WSTG_SZ 16384     // WH 8KB + WL 8KB
#define B_HI    0
#define B_LO    8192
#define W_HI    0
#define W_LO    8192
#define W_BASE  (3 * BSTG_SZ)
#define DSMEM_BYTES (3 * BSTG_SZ + 2 * WSTG_SZ + 1024)

__device__ float g_e1[GB * GN];
__device__ float g_f1[GB * GN];
__device__ float g_e2[GB * GN];
__device__ float g_f2[GB * GN];
__device__ __nv_bfloat16 g_hh[GB * GN * GC];
__device__ __nv_bfloat16 g_hl[GB * GN * GC];

// ---------------------------------------------------------------- helpers
static __device__ __forceinline__ uint32_t smem_u32(const void* p) {
    uint32_t a;
    asm("{ .reg .u64 t; cvta.to.shared.u64 t, %1; cvt.u32.u64 %0, t; }"
        : "=r"(a) : "l"(p));
    return a;
}
// packs {lo -> low16, hi -> high16} with round-to-nearest
static __device__ __forceinline__ uint32_t cvt_bf16x2(float lo, float hi) {
    uint32_t r;
    asm("cvt.rn.bf16x2.f32 %0, %1, %2;" : "=r"(r) : "f"(hi), "f"(lo));
    return r;
}
static __device__ __forceinline__ uint32_t sw128(uint32_t b) {
    return b ^ ((b >> 3) & 0x70);
}
#define CP16(dst, src) \
    asm volatile("cp.async.cg.shared.global [%0], [%1], 16;" \
                 :: "r"(dst), "l"(src) : "memory")
#define CP_COMMIT() asm volatile("cp.async.commit_group;" ::: "memory")
#define CP_WAIT1()  asm volatile("cp.async.wait_group 1;" ::: "memory")

static __device__ __forceinline__ void ldmx4(uint32_t* r, uint32_t addr) {
    asm volatile("ldmatrix.sync.aligned.m8n8.x4.shared.b16 {%0,%1,%2,%3}, [%4];"
        : "=r"(r[0]), "=r"(r[1]), "=r"(r[2]), "=r"(r[3]) : "r"(addr));
}
static __device__ __forceinline__ void ldmx4t(uint32_t* r, uint32_t addr) {
    asm volatile("ldmatrix.sync.aligned.m8n8.x4.trans.shared.b16 {%0,%1,%2,%3}, [%4];"
        : "=r"(r[0]), "=r"(r[1]), "=r"(r[2]), "=r"(r[3]) : "r"(addr));
}
static __device__ __forceinline__ void mma_bf16(float* d, const uint32_t* a,
                                                uint32_t b0, uint32_t b1) {
    asm volatile(
        "mma.sync.aligned.m16n8k16.row.col.f32.bf16.bf16.f32 "
        "{%0,%1,%2,%3}, {%4,%5,%6,%7}, {%8,%9}, {%0,%1,%2,%3};"
        : "+f"(d[0]), "+f"(d[1]), "+f"(d[2]), "+f"(d[3])
        : "r"(a[0]), "r"(a[1]), "r"(a[2]), "r"(a[3]), "r"(b0), "r"(b1));
}

// ---------------------------------------------------------------- kernel 1
// E/F score factors + h hi/lo bf16 split.
__global__ void gat_scores_kernel(const float* __restrict__ h,
                                  const float* __restrict__ a) {
    int warp = (blockIdx.x * blockDim.x + threadIdx.x) >> 5;
    int lane = threadIdx.x & 31;
    if (warp >= GB * GN) return;
    const float* row = h + (size_t)warp * GC;
    float v0 = row[lane];
    float v1 = row[lane + 32];

    __nv_bfloat16 h0 = __float2bfloat16_rn(v0);
    __nv_bfloat16 h1 = __float2bfloat16_rn(v1);
    g_hh[warp * GC + lane]      = h0;
    g_hh[warp * GC + lane + 32] = h1;
    g_hl[warp * GC + lane]      = __float2bfloat16_rn(v0 - __bfloat162float(h0));
    g_hl[warp * GC + lane + 32] = __float2bfloat16_rn(v1 - __bfloat162float(h1));

    float p1 = v0 * a[lane]      + v1 * a[lane + 32];
    float p2 = v0 * a[GC + lane] + v1 * a[GC + lane + 32];
#pragma unroll
    for (int o = 16; o; o >>= 1) {
        p1 += __shfl_xor_sync(0xFFFFFFFFu, p1, o);
        p2 += __shfl_xor_sync(0xFFFFFFFFu, p2, o);
    }
    const float LOG2E = 1.4426950408889634f;
    if (lane == 0) {
        float t1 = p1 * LOG2E, t2 = p2 * LOG2E;
        g_e1[warp] = exp2f(t1);
        g_f1[warp] = exp2f(0.2f * t1);
        g_e2[warp] = exp2f(t2);
        g_f2[warp] = exp2f(0.2f * t2);
    }
}

// ---------------------------------------------------------------- prefetch
static __device__ __forceinline__ void prefetch_tile(uint32_t bstg,
                                                     int b, int j0, int t) {
    const __nv_bfloat16* hh = g_hh + ((size_t)b * GN + j0) * GC;
    const __nv_bfloat16* hl = g_hl + ((size_t)b * GN + j0) * GC;
#pragma unroll
    for (int k = 0; k < 2; k++) {
        int q = t + 256 * k;
        int j = q >> 3, cc = q & 7;
        uint32_t off = sw128((uint32_t)(j * 128 + cc * 16));
        CP16(bstg + B_HI + off, hh + j * GC + cc * 8);
        CP16(bstg + B_LO + off, hl + j * GC + cc * 8);
    }
}

// ---------------------------------------------------------------- kernel 2
__global__ __launch_bounds__(256, 2)
void gat_main_kernel(const float* __restrict__ adj,
                     float* __restrict__ out) {
    extern __shared__ char smem_raw[];
    __shared__ float sh_l[TI];

    const int t    = threadIdx.x;
    const int wid  = t >> 5;
    const int lane = t & 31;
    const int b    = blockIdx.y;
    const int i0   = blockIdx.x * TI;
    const int wm   = wid & 3;
    const int wn   = wid >> 2;

    uint32_t raw_u32 = smem_u32(smem_raw);
    uint32_t sbu = (raw_u32 + 1023u) & ~1023u;

    if (t < TI) sh_l[t] = 0.0f;

    const int r0  = t >> 4;
    const int jj0 = (t & 15) * 4;
    float E1[4], F1[4];
#pragma unroll
    for (int k = 0; k < 4; k++) {
        int row = b * GN + i0 + r0 + 16 * k;
        E1[k] = g_e1[row];
        F1[k] = g_f1[row];
    }
    float lsum[4] = {0.f, 0.f, 0.f, 0.f};

    const float* ap0 = adj + (size_t)(i0 + r0)      * GN + jj0;
    const float* ap1 = ap0 + (size_t)16 * GN;
    const float* ap2 = ap0 + (size_t)32 * GN;
    const float* ap3 = ap0 + (size_t)48 * GN;
    const float* e2p = g_e2 + b * GN + jj0;
    const float* f2p = g_f2 + b * GN + jj0;

    const uint32_t xr     = (uint32_t)(lane & 7) << 4;
    const uint32_t a_base = (uint32_t)((wm * 16 + (lane & 15)) * 128 + (lane & 16));
    const uint32_t b_base = (uint32_t)((lane & 15) * 128 + (lane & 16) + wn * 64);
    const uint32_t wbase  = sw128((uint32_t)(r0 * 128 + jj0 * 2));

    float acc[4][4];
#pragma unroll
    for (int nn = 0; nn < 4; nn++)
#pragma unroll
        for (int q = 0; q < 4; q++) acc[nn][q] = 0.0f;

    // prologue: B(0) and B(1) prefetch; adj(0)+E2/F2(0) into regs
    prefetch_tile(sbu + 0 * BSTG_SZ, b, 0, t);
    CP_COMMIT();
    prefetch_tile(sbu + 1 * BSTG_SZ, b, TJ, t);
    CP_COMMIT();
    float4 av[4];
    av[0] = __ldg((const float4*)ap0);
    av[1] = __ldg((const float4*)ap1);
    av[2] = __ldg((const float4*)ap2);
    av[3] = __ldg((const float4*)ap3);
    float4 e2v = __ldg((const float4*)e2p);
    float4 f2v = __ldg((const float4*)f2p);

    int bs = 0;    // B stage of current tile (tile % 3)
    for (int tile = 0; tile < NTILES; tile++) {
        const int s = tile & 1;
        const uint32_t wstg = sbu + W_BASE + s * WSTG_SZ;
        const uint32_t bstg = sbu + bs * BSTG_SZ;

        // ---- phase B: w = mask * max(E1*E2, F1*F2), hi/lo bf16, SW128 ----
#pragma unroll
        for (int k = 0; k < 4; k++) {
            float w0 = (av[k].x > THRESH) ? fmaxf(E1[k] * e2v.x, F1[k] * f2v.x) : 0.0f;
            float w1 = (av[k].y > THRESH) ? fmaxf(E1[k] * e2v.y, F1[k] * f2v.y) : 0.0f;
            float w2 = (av[k].z > THRESH) ? fmaxf(E1[k] * e2v.z, F1[k] * f2v.z) : 0.0f;
            float w3 = (av[k].w > THRESH) ? fmaxf(E1[k] * e2v.w, F1[k] * f2v.w) : 0.0f;
            lsum[k] += (w0 + w1) + (w2 + w3);
            uint32_t h01 = cvt_bf16x2(w0, w1);
            uint32_t h23 = cvt_bf16x2(w2, w3);
            float f0 = __uint_as_float(h01 << 16);
            float f1 = __uint_as_float(h01 & 0xFFFF0000u);
            float f2 = __uint_as_float(h23 << 16);
            float f3 = __uint_as_float(h23 & 0xFFFF0000u);
            uint32_t l01 = cvt_bf16x2(w0 - f0, w1 - f1);
            uint32_t l23 = cvt_bf16x2(w2 - f2, w3 - f3);
            asm volatile("st.shared.v2.b32 [%0], {%1,%2};"
                         :: "r"(wstg + W_HI + wbase + k * 2048),
                            "r"(h01), "r"(h23) : "memory");
            asm volatile("st.shared.v2.b32 [%0], {%1,%2};"
                         :: "r"(wstg + W_LO + wbase + k * 2048),
                            "r"(l01), "r"(l23) : "memory");
        }

        // ---- issue adj + E2/F2 loads for NEXT tile (hidden under MMA) ----
        {
            int jn = (tile + 1 < NTILES) ? (tile + 1) * TJ : 0;
            av[0] = __ldg((const float4*)(ap0 + jn));
            av[1] = __ldg((const float4*)(ap1 + jn));
            av[2] = __ldg((const float4*)(ap2 + jn));
            av[3] = __ldg((const float4*)(ap3 + jn));
            e2v   = __ldg((const float4*)(e2p + jn));
            f2v   = __ldg((const float4*)(f2p + jn));
        }

        CP_WAIT1();        // B(tile) done (B(tile+1) may remain in flight)
        __syncthreads();   // W + B visible; all warps past mma(tile-1)

        // ---- prefetch B(tile+2) into the stage freed by mma(tile-1) ----
        if (tile + 2 < NTILES) {
            int bs2 = bs + 2; if (bs2 >= 3) bs2 -= 3;
            prefetch_tile(sbu + bs2 * BSTG_SZ, b, (tile + 2) * TJ, t);
        }
        CP_COMMIT();

        // ---- MMA phase: 3-term bf16, warp tile 16x32 ----
        {
            const uint32_t whb = wstg + W_HI;
            const uint32_t wlb = wstg + W_LO;
            const uint32_t bhb = bstg + B_HI;
            const uint32_t blb = bstg + B_LO;
#pragma unroll
            for (int kk = 0; kk < 4; kk++) {
                uint32_t ahi[4], alo[4];
                uint32_t a_off = (a_base + kk * 32) ^ xr;
                ldmx4(ahi, whb + a_off);
                ldmx4(alo, wlb + a_off);
                uint32_t bh[8], bl[8];
#pragma unroll
                for (int np = 0; np < 2; np++) {
                    uint32_t b_off = (b_base + kk * 2048 + np * 32) ^ xr;
                    ldmx4t(&bh[np * 4], bhb + b_off);
                    ldmx4t(&bl[np * 4], blb + b_off);
                }
#pragma unroll
                for (int nn = 0; nn < 4; nn++) {
                    int base = (nn >> 1) * 4 + (nn & 1) * 2;
                    mma_bf16(acc[nn], ahi, bh[base], bh[base + 1]);
                    mma_bf16(acc[nn], ahi, bl[base], bl[base + 1]);
                    mma_bf16(acc[nn], alo, bh[base], bh[base + 1]);
                }
            }
        }

        bs = (bs == 2) ? 0 : bs + 1;
    }

    // ---- row sums ----
#pragma unroll
    for (int k = 0; k < 4; k++)
        atomicAdd(&sh_l[r0 + 16 * k], lsum[k]);
    __syncthreads();

    // ---- epilogue: normalize + ELU + store ----
    {
        int g  = lane >> 2;
        int qc = (lane & 3) * 2;
        int ra = wm * 16 + g;
        int rb = ra + 8;
        float la = 1.0f / sh_l[ra];
        float lb = 1.0f / sh_l[rb];
        float* oa = out + ((size_t)b * GN + i0 + ra) * GC;
        float* ob = out + ((size_t)b * GN + i0 + rb) * GC;
#pragma unroll
        for (int nn = 0; nn < 4; nn++) {
            int c = wn * 32 + nn * 8 + qc;
            float v0 = acc[nn][0] * la, v1 = acc[nn][1] * la;
            float v2 = acc[nn][2] * lb, v3 = acc[nn][3] * lb;
            float2 pa, pb;
            pa.x = (v0 > 0.f) ? v0 : expm1f(v0);
            pa.y = (v1 > 0.f) ? v1 : expm1f(v1);
            pb.x = (v2 > 0.f) ? v2 : expm1f(v2);
            pb.y = (v3 > 0.f) ? v3 : expm1f(v3);
            *(float2*)(oa + c) = pa;
            *(float2*)(ob + c) = pb;
        }
    }
}

// ---------------------------------------------------------------- launch
extern "C" void kernel_launch(void* const* d_in, const int* in_sizes, int n_in,
                              void* d_out, int out_size) {
    const float* input = (const float*)d_in[0];   // (B, N, C)
    const float* adj   = (const float*)d_in[1];   // (N, N)
    const float* a     = (const float*)d_in[2];   // (2C, 1)
    float* out = (float*)d_out;                   // (B, N, C)

    gat_scores_kernel<<<(GB * GN) / 8, 256>>>(input, a);

    cudaFuncSetAttribute(gat_main_kernel,
                         cudaFuncAttributeMaxDynamicSharedMemorySize, DSMEM_BYTES);
    dim3 grid(GN / TI, GB);
    gat_main_kernel<<<grid, 256, DSMEM_BYTES>>>(adj, out);
}

// round 17
// speedup vs baseline: 1.6938x; 1.1111x over previous
#include <cuda_runtime.h>
#include <cuda_bf16.h>
#include <cstdint>

// GAT: B=4, N=4096, C=64
// out = elu( softmax_j( mask(adj>0.5, lrelu(s1+s2)) ) @ h )
// R15: fragment-direct W. Phase B computes mma A-fragments in registers
//      (K-permuted so adj/E2/F2 loads are contiguous float4); no W smem,
//      no A-side ldmatrix. Warp = (wm rows, wk K-half); partner accs summed
//      in epilogue. 3-stage B cp.async as R14. exp factorization kept.

#define GB 4
#define GN 4096
#define GC 64
#define TI 64
#define TJ 64
#define NTILES (GN / TJ)
#define THRESH 0.5f

#define BSTG_SZ 16384     // BH 8KB + BL 8KB
#define B_HI    0
#define B_LO    8192
#define DSMEM_BYTES (3 * BSTG_SZ + 1024)

__device__ float g_e1[GB * GN];
__device__ float g_f1[GB * GN];
__device__ float g_e2[GB * GN];
__device__ float g_f2[GB * GN];
__device__ __nv_bfloat16 g_hh[GB * GN * GC];
__device__ __nv_bfloat16 g_hl[GB * GN * GC];

// ---------------------------------------------------------------- helpers
static __device__ __forceinline__ uint32_t smem_u32(const void* p) {
    uint32_t a;
    asm("{ .reg .u64 t; cvta.to.shared.u64 t, %1; cvt.u32.u64 %0, t; }"
        : "=r"(a) : "l"(p));
    return a;
}
// packs {lo -> low16, hi -> high16} with round-to-nearest
static __device__ __forceinline__ uint32_t cvt_bf16x2(float lo, float hi) {
    uint32_t r;
    asm("cvt.rn.bf16x2.f32 %0, %1, %2;" : "=r"(r) : "f"(hi), "f"(lo));
    return r;
}
static __device__ __forceinline__ uint32_t sw128(uint32_t b) {
    return b ^ ((b >> 3) & 0x70);
}
#define CP16(dst, src) \
    asm volatile("cp.async.cg.shared.global [%0], [%1], 16;" \
                 :: "r"(dst), "l"(src) : "memory")
#define CP_COMMIT() asm volatile("cp.async.commit_group;" ::: "memory")
#define CP_WAIT1()  asm volatile("cp.async.wait_group 1;" ::: "memory")
#define CP_WAIT0()  asm volatile("cp.async.wait_group 0;" ::: "memory")

static __device__ __forceinline__ void ldmx4t(uint32_t* r, uint32_t addr) {
    asm volatile("ldmatrix.sync.aligned.m8n8.x4.trans.shared.b16 {%0,%1,%2,%3}, [%4];"
        : "=r"(r[0]), "=r"(r[1]), "=r"(r[2]), "=r"(r[3]) : "r"(addr));
}
static __device__ __forceinline__ void mma_bf16(float* d, const uint32_t* a,
                                                uint32_t b0, uint32_t b1) {
    asm volatile(
        "mma.sync.aligned.m16n8k16.row.col.f32.bf16.bf16.f32 "
        "{%0,%1,%2,%3}, {%4,%5,%6,%7}, {%8,%9}, {%0,%1,%2,%3};"
        : "+f"(d[0]), "+f"(d[1]), "+f"(d[2]), "+f"(d[3])
        : "r"(a[0]), "r"(a[1]), "r"(a[2]), "r"(a[3]), "r"(b0), "r"(b1));
}

// ---------------------------------------------------------------- kernel 1
__global__ void gat_scores_kernel(const float* __restrict__ h,
                                  const float* __restrict__ a) {
    int warp = (blockIdx.x * blockDim.x + threadIdx.x) >> 5;
    int lane = threadIdx.x & 31;
    if (warp >= GB * GN) return;
    const float* row = h + (size_t)warp * GC;
    float v0 = row[lane];
    float v1 = row[lane + 32];

    __nv_bfloat16 h0 = __float2bfloat16_rn(v0);
    __nv_bfloat16 h1 = __float2bfloat16_rn(v1);
    g_hh[warp * GC + lane]      = h0;
    g_hh[warp * GC + lane + 32] = h1;
    g_hl[warp * GC + lane]      = __float2bfloat16_rn(v0 - __bfloat162float(h0));
    g_hl[warp * GC + lane + 32] = __float2bfloat16_rn(v1 - __bfloat162float(h1));

    float p1 = v0 * a[lane]      + v1 * a[lane + 32];
    float p2 = v0 * a[GC + lane] + v1 * a[GC + lane + 32];
#pragma unroll
    for (int o = 16; o; o >>= 1) {
        p1 += __shfl_xor_sync(0xFFFFFFFFu, p1, o);
        p2 += __shfl_xor_sync(0xFFFFFFFFu, p2, o);
    }
    const float LOG2E = 1.4426950408889634f;
    if (lane == 0) {
        float t1 = p1 * LOG2E, t2 = p2 * LOG2E;
        g_e1[warp] = exp2f(t1);
        g_f1[warp] = exp2f(0.2f * t1);
        g_e2[warp] = exp2f(t2);
        g_f2[warp] = exp2f(0.2f * t2);
    }
}

// ---------------------------------------------------------------- prefetch
// h hi/lo tiles, K-major SW128, rows K-PERMUTED to match fragment-direct A:
// logical j (within 16-group) stored at physical row f where
// j = 4*((f>>1)&3) + 2*(f>>3) + (f&1).
static __device__ __forceinline__ void prefetch_tile(uint32_t bstg,
                                                     int b, int j0, int t) {
    const __nv_bfloat16* hh = g_hh + ((size_t)b * GN + j0) * GC;
    const __nv_bfloat16* hl = g_hl + ((size_t)b * GN + j0) * GC;
#pragma unroll
    for (int k = 0; k < 2; k++) {
        int qq = t + 256 * k;
        int j = qq >> 3, cc = qq & 7;
        int jl = j & 15;
        int jp = (j & 48) | (2 * ((jl >> 2) & 3) + 8 * ((jl >> 1) & 1) + (jl & 1));
        uint32_t off = sw128((uint32_t)(jp * 128 + cc * 16));
        CP16(bstg + B_HI + off, hh + j * GC + cc * 8);
        CP16(bstg + B_LO + off, hl + j * GC + cc * 8);
    }
}

// ---------------------------------------------------------------- kernel 2
__global__ __launch_bounds__(256, 2)
void gat_main_kernel(const float* __restrict__ adj,
                     float* __restrict__ out) {
    extern __shared__ char smem_raw[];
    __shared__ float sh_l[TI];

    const int t    = threadIdx.x;
    const int wid  = t >> 5;
    const int lane = t & 31;
    const int b    = blockIdx.y;
    const int i0   = blockIdx.x * TI;
    const int wm   = wid & 3;    // row group: rows wm*16 .. +15
    const int wk   = wid >> 2;   // K half:   cols wk*32 .. +31
    const int g    = lane >> 2;  // fragment row within group
    const int q    = lane & 3;   // fragment quad

    uint32_t raw_u32 = smem_u32(smem_raw);
    uint32_t sbu = (raw_u32 + 1023u) & ~1023u;

    if (t < TI) sh_l[t] = 0.0f;

    const int rlo = wm * 16 + g;          // local row (lo)
    const int rhi = rlo + 8;              // local row (hi)
    const float E1g = g_e1[b * GN + i0 + rlo];
    const float F1g = g_f1[b * GN + i0 + rlo];
    const float E1h = g_e1[b * GN + i0 + rhi];
    const float F1h = g_f1[b * GN + i0 + rhi];

    // this thread's logical j-columns per kl: wk*32 + kl*16 + q*4 .. +3
    const float* apg = adj + (size_t)(i0 + rlo) * GN + wk * 32 + q * 4;
    const float* aph = apg + (size_t)8 * GN;
    const float* e2p = g_e2 + b * GN + wk * 32 + q * 4;
    const float* f2p = g_f2 + b * GN + wk * 32 + q * 4;

    const uint32_t xr     = (uint32_t)(lane & 7) << 4;
    const uint32_t b_base = (uint32_t)((lane & 15) * 128 + (lane & 16));

    float acc[8][4];
#pragma unroll
    for (int nn = 0; nn < 8; nn++)
#pragma unroll
        for (int c = 0; c < 4; c++) acc[nn][c] = 0.0f;

    float lsg = 0.f, lsh = 0.f;

    // prologue: B(0), B(1) prefetch; adj/E2/F2(0) regs
    prefetch_tile(sbu + 0 * BSTG_SZ, b, 0, t);
    CP_COMMIT();
    prefetch_tile(sbu + 1 * BSTG_SZ, b, TJ, t);
    CP_COMMIT();
    float4 avg[2], avh[2], e2v[2], f2v[2];
#pragma unroll
    for (int kl = 0; kl < 2; kl++) {
        avg[kl] = __ldg((const float4*)(apg + kl * 16));
        avh[kl] = __ldg((const float4*)(aph + kl * 16));
        e2v[kl] = __ldg((const float4*)(e2p + kl * 16));
        f2v[kl] = __ldg((const float4*)(f2p + kl * 16));
    }

    int bs = 0;
    for (int tile = 0; tile < NTILES; tile++) {
        // ---- phase B: A-fragments (hi/lo bf16) directly in registers ----
        uint32_t ahi[2][4], alo[2][4];
#pragma unroll
        for (int kl = 0; kl < 2; kl++) {
            float4 aG = avg[kl], aH = avh[kl];
            float4 e2 = e2v[kl], f2 = f2v[kl];
            float w0 = (aG.x > THRESH) ? fmaxf(E1g * e2.x, F1g * f2.x) : 0.f;
            float w1 = (aG.y > THRESH) ? fmaxf(E1g * e2.y, F1g * f2.y) : 0.f;
            float w2 = (aG.z > THRESH) ? fmaxf(E1g * e2.z, F1g * f2.z) : 0.f;
            float w3 = (aG.w > THRESH) ? fmaxf(E1g * e2.w, F1g * f2.w) : 0.f;
            float v0 = (aH.x > THRESH) ? fmaxf(E1h * e2.x, F1h * f2.x) : 0.f;
            float v1 = (aH.y > THRESH) ? fmaxf(E1h * e2.y, F1h * f2.y) : 0.f;
            float v2 = (aH.z > THRESH) ? fmaxf(E1h * e2.z, F1h * f2.z) : 0.f;
            float v3 = (aH.w > THRESH) ? fmaxf(E1h * e2.w, F1h * f2.w) : 0.f;
            lsg += (w0 + w1) + (w2 + w3);
            lsh += (v0 + v1) + (v2 + v3);
            uint32_t p01 = cvt_bf16x2(w0, w1);
            uint32_t p23 = cvt_bf16x2(w2, w3);
            uint32_t q01 = cvt_bf16x2(v0, v1);
            uint32_t q23 = cvt_bf16x2(v2, v3);
            ahi[kl][0] = p01; ahi[kl][1] = q01;
            ahi[kl][2] = p23; ahi[kl][3] = q23;
            float t0 = __uint_as_float(p01 << 16);
            float t1 = __uint_as_float(p01 & 0xFFFF0000u);
            float t2 = __uint_as_float(p23 << 16);
            float t3 = __uint_as_float(p23 & 0xFFFF0000u);
            float s0 = __uint_as_float(q01 << 16);
            float s1 = __uint_as_float(q01 & 0xFFFF0000u);
            float s2 = __uint_as_float(q23 << 16);
            float s3 = __uint_as_float(q23 & 0xFFFF0000u);
            alo[kl][0] = cvt_bf16x2(w0 - t0, w1 - t1);
            alo[kl][1] = cvt_bf16x2(v0 - s0, v1 - s1);
            alo[kl][2] = cvt_bf16x2(w2 - t2, w3 - t3);
            alo[kl][3] = cvt_bf16x2(v2 - s2, v3 - s3);
        }

        // ---- issue adj/E2/F2 loads for NEXT tile (hidden under MMA) ----
        {
            int jn = (tile + 1 < NTILES) ? (tile + 1) * TJ : 0;
#pragma unroll
            for (int kl = 0; kl < 2; kl++) {
                avg[kl] = __ldg((const float4*)(apg + jn + kl * 16));
                avh[kl] = __ldg((const float4*)(aph + jn + kl * 16));
                e2v[kl] = __ldg((const float4*)(e2p + jn + kl * 16));
                f2v[kl] = __ldg((const float4*)(f2p + jn + kl * 16));
            }
        }

        CP_WAIT1();        // B(tile) ready (B(tile+1) may remain in flight)
        __syncthreads();   // B visible; all warps past MMA(tile-1)

        // ---- prefetch B(tile+2) into the stage freed by MMA(tile-1) ----
        if (tile + 2 < NTILES) {
            int bs2 = bs + 2; if (bs2 >= 3) bs2 -= 3;
            prefetch_tile(sbu + bs2 * BSTG_SZ, b, (tile + 2) * TJ, t);
        }
        CP_COMMIT();

        // ---- MMA: this warp's K-half, all 64 n-cols ----
        {
            const uint32_t bstg = sbu + bs * BSTG_SZ;
#pragma unroll
            for (int kl = 0; kl < 2; kl++) {
                uint32_t krow = (uint32_t)((wk * 2 + kl) * 2048);
#pragma unroll
                for (int np = 0; np < 4; np++) {
                    uint32_t boff = (b_base + krow + np * 32) ^ xr;
                    uint32_t bh[4], bl[4];
                    ldmx4t(bh, bstg + B_HI + boff);
                    ldmx4t(bl, bstg + B_LO + boff);
                    int nn = np * 2;
                    mma_bf16(acc[nn],     ahi[kl], bh[0], bh[1]);
                    mma_bf16(acc[nn],     ahi[kl], bl[0], bl[1]);
                    mma_bf16(acc[nn],     alo[kl], bh[0], bh[1]);
                    mma_bf16(acc[nn + 1], ahi[kl], bh[2], bh[3]);
                    mma_bf16(acc[nn + 1], ahi[kl], bl[2], bl[3]);
                    mma_bf16(acc[nn + 1], alo[kl], bh[2], bh[3]);
                }
            }
        }

        bs = (bs == 2) ? 0 : bs + 1;
    }

    CP_WAIT0();

    // ---- row sums: reduce over quad lanes, then shared ----
    lsg += __shfl_xor_sync(0xFFFFFFFFu, lsg, 1);
    lsg += __shfl_xor_sync(0xFFFFFFFFu, lsg, 2);
    lsh += __shfl_xor_sync(0xFFFFFFFFu, lsh, 1);
    lsh += __shfl_xor_sync(0xFFFFFFFFu, lsh, 2);
    if (q == 0) {
        atomicAdd(&sh_l[rlo], lsg);
        atomicAdd(&sh_l[rhi], lsh);
    }
    __syncthreads();

    // ---- epilogue: sum partner (wk) accs via smem, normalize+ELU+store ----
    const uint32_t red  = sbu;                 // reuse B stage 0 (16 KB)
    const uint32_t skew = (uint32_t)(g * 32);  // (row&7)*32 bank skew
    if (wk == 1) {
#pragma unroll
        for (int nn = 0; nn < 8; nn++) {
            uint32_t co = ((uint32_t)(nn * 32 + q * 8)) ^ skew;
            asm volatile("st.shared.v2.f32 [%0], {%1,%2};"
                         :: "r"(red + rlo * 256 + co),
                            "f"(acc[nn][0]), "f"(acc[nn][1]) : "memory");
            asm volatile("st.shared.v2.f32 [%0], {%1,%2};"
                         :: "r"(red + rhi * 256 + co),
                            "f"(acc[nn][2]), "f"(acc[nn][3]) : "memory");
        }
    }
    __syncthreads();
    if (wk == 0) {
        float la = 1.0f / sh_l[rlo];
        float lb = 1.0f / sh_l[rhi];
        float* oa = out + ((size_t)b * GN + i0 + rlo) * GC;
        float* ob = out + ((size_t)b * GN + i0 + rhi) * GC;
#pragma unroll
        for (int nn = 0; nn < 8; nn++) {
            uint32_t co = ((uint32_t)(nn * 32 + q * 8)) ^ skew;
            float p0, p1, p2, p3;
            asm volatile("ld.shared.v2.f32 {%0,%1}, [%2];"
                         : "=f"(p0), "=f"(p1) : "r"(red + rlo * 256 + co));
            asm volatile("ld.shared.v2.f32 {%0,%1}, [%2];"
                         : "=f"(p2), "=f"(p3) : "r"(red + rhi * 256 + co));
            float v0 = (acc[nn][0] + p0) * la, v1 = (acc[nn][1] + p1) * la;
            float v2 = (acc[nn][2] + p2) * lb, v3 = (acc[nn][3] + p3) * lb;
            float2 A, Bv;
            A.x  = (v0 > 0.f) ? v0 : expm1f(v0);
            A.y  = (v1 > 0.f) ? v1 : expm1f(v1);
            Bv.x = (v2 > 0.f) ? v2 : expm1f(v2);
            Bv.y = (v3 > 0.f) ? v3 : expm1f(v3);
            int c = nn * 8 + q * 2;
            *(float2*)(oa + c) = A;
            *(float2*)(ob + c) = Bv;
        }
    }
}

// ---------------------------------------------------------------- launch
extern "C" void kernel_launch(void* const* d_in, const int* in_sizes, int n_in,
                              void* d_out, int out_size) {
    const float* input = (const float*)d_in[0];   // (B, N, C)
    const float* adj   = (const float*)d_in[1];   // (N, N)
    const float* a     = (const float*)d_in[2];   // (2C, 1)
    float* out = (float*)d_out;                   // (B, N, C)

    gat_scores_kernel<<<(GB * GN) / 8, 256>>>(input, a);

    cudaFuncSetAttribute(gat_main_kernel,
                         cudaFuncAttributeMaxDynamicSharedMemorySize, DSMEM_BYTES);
    dim3 grid(GN / TI, GB);
    gat_main_kernel<<<grid, 256, DSMEM_BYTES>>>(adj, out);
}